// round 12
// baseline (speedup 1.0000x reference)
#include <cuda_runtime.h>
#include <cuda.h>
#include <cuda_bf16.h>
#include <cstdint>

// Problem dims
#define VD   2048
#define QD   1024
#define HID  1024
#define BB   64
#define KK   12
#define NN   36
#define MROWS (BB*KK*NN)   // 27648
#define MQ    (BB*KK)      // 768

// ---------------- scratch (no cudaMalloc allowed) ----------------
__device__ float g_norm2[2];
__device__ float g_logits[MROWS];
__device__ float g_hq[MQ * HID];
__device__ float g_hq4[4][MQ * HID];                                // split-K slices
__device__ __align__(1024) __nv_bfloat16 g_vb[(size_t)MROWS * VD];  // 113 MB bf16 v
__device__ __align__(1024) __nv_bfloat16 g_w1b[(size_t)HID * VD];   // 4 MB bf16 W1[:, :VD]

// ---------------------------------------------------------------------------
__device__ __forceinline__ uint32_t pack_bf16(float x, float y) {
    __nv_bfloat162 h = __floats2bfloat162_rn(x, y);
    return *reinterpret_cast<uint32_t*>(&h);
}

// ---------------------------------------------------------------------------
// mma helpers
// ---------------------------------------------------------------------------
__device__ __forceinline__ void ldsm4(uint32_t& r0, uint32_t& r1, uint32_t& r2,
                                      uint32_t& r3, uint32_t addr) {
    asm volatile("ldmatrix.sync.aligned.m8n8.x4.shared.b16 {%0,%1,%2,%3}, [%4];"
                 : "=r"(r0), "=r"(r1), "=r"(r2), "=r"(r3)
                 : "r"(addr));
}

__device__ __forceinline__ void mma16816(float* c, const uint32_t* a,
                                         const uint32_t* b) {
    asm volatile(
        "mma.sync.aligned.m16n8k16.row.col.f32.bf16.bf16.f32 "
        "{%0,%1,%2,%3}, {%4,%5,%6,%7}, {%8,%9}, {%0,%1,%2,%3};"
        : "+f"(c[0]), "+f"(c[1]), "+f"(c[2]), "+f"(c[3])
        : "r"(a[0]), "r"(a[1]), "r"(a[2]), "r"(a[3]), "r"(b[0]), "r"(b[1]));
}

// swizzled elem offset in a [rows x 64] bf16 tile (128B rows, 16B chunks)
__device__ __forceinline__ int sw_off(int r, int c) {
    return r * 64 + ((c ^ (r & 7)) << 3);
}

// ---------------------------------------------------------------------------
// Fused prep kernel: block-role dispatch.
//   [0, HQ)          : hq split-K GEMM slices (overlaps with conversion)
//   [HQ, +NV)        : convert v -> bf16 (DRAM-bound long pole)
//   [+NV, +NW)       : convert W1[:, :VD] -> bf16
//   [+NW, +256)      : norm W1 (grid-stride partial + atomic; g_norm2 memset'd
//                      by a graph memset node before this kernel)
//   [+256, +260)     : norm W2
//   [+260, +388)     : zero g_logits
// ---------------------------------------------------------------------------
#define HQ_BLK 192                          // 8n x 6m x 4ksplit
#define NV_BLK (MROWS * VD / 8 / 256)       // 27648
#define NW_BLK (HID * VD / 8 / 256)         // 1024
#define NORM1_BLK 256
#define NORM2_BLK 4
#define ZERO_BLK 128
#define PREP_GRID (HQ_BLK + NV_BLK + NW_BLK + NORM1_BLK + NORM2_BLK + ZERO_BLK)

#define BMH 128
#define BKT 64

__device__ __forceinline__ void norm_partial(const float* __restrict__ p,
                                             int n, int slot, int nblocks,
                                             int bid) {
    float s = 0.f;
    for (int i = bid * 256 + threadIdx.x; i < n; i += nblocks * 256) {
        float v = p[i];
        s += v * v;
    }
    for (int o = 16; o; o >>= 1) s += __shfl_xor_sync(0xFFFFFFFFu, s, o);
    __shared__ float sh[8];
    int lane = threadIdx.x & 31, w = threadIdx.x >> 5;
    if (!lane) sh[w] = s;
    __syncthreads();
    if (!w) {
        s = (lane < 8) ? sh[lane] : 0.f;
        for (int o = 4; o; o >>= 1) s += __shfl_xor_sync(0xFFFFFFFFu, s, o);
        if (!lane) atomicAdd(&g_norm2[slot], s);
    }
}

// hq GEMM slice: 128x128x256 per block, no prefetch (KT=4, latency amortized)
__device__ void hq_body(int bid, const float* __restrict__ q,
                        const float* __restrict__ W1,
                        __nv_bfloat16* sA, __nv_bfloat16* sB) {
    const int tid = threadIdx.x;
    const int lane = tid & 31;
    const int wid = tid >> 5;
    const int nt = bid & 7;
    const int rest = bid >> 3;        // 0..23
    const int mt = rest % 6;
    const int ksp = rest / 6;         // 0..3
    const int m0 = mt * BMH;
    const int n0 = nt * BMH;
    const int wm = (wid >> 2) * 64;
    const int wn = (wid & 3) * 32;
    const int kbase = ksp * 256;
    const int KT = 256 / BKT;         // 4

    const float* Ag = q + kbase;
    const int kofs = VD + kbase;

    float acc[4][4][4];
#pragma unroll
    for (int a = 0; a < 4; a++)
#pragma unroll
        for (int b = 0; b < 4; b++)
#pragma unroll
            for (int c = 0; c < 4; c++) acc[a][b][c] = 0.f;

    int lr[4], lc[4];
#pragma unroll
    for (int i = 0; i < 4; i++) {
        int ch = tid + i * 256;
        lr[i] = ch >> 3;
        lc[i] = ch & 7;
    }

    const uint32_t sAb = (uint32_t)__cvta_generic_to_shared(sA);
    const uint32_t sBb = (uint32_t)__cvta_generic_to_shared(sB);

    for (int kt = 0; kt < KT; kt++) {
        __syncthreads();
        int k0 = kt * BKT;
#pragma unroll
        for (int i = 0; i < 4; i++) {
            const float4* ap = reinterpret_cast<const float4*>(
                Ag + (size_t)(m0 + lr[i]) * QD + k0 + lc[i] * 8);
            float4 a0 = ap[0], a1 = ap[1];
            const float4* bp = reinterpret_cast<const float4*>(
                W1 + (size_t)(n0 + lr[i]) * (VD + QD) + kofs + k0 + lc[i] * 8);
            float4 b0 = bp[0], b1v = bp[1];
            int off = sw_off(lr[i], lc[i]);
            uint4 va;
            va.x = pack_bf16(a0.x, a0.y); va.y = pack_bf16(a0.z, a0.w);
            va.z = pack_bf16(a1.x, a1.y); va.w = pack_bf16(a1.z, a1.w);
            *reinterpret_cast<uint4*>(&sA[off]) = va;
            uint4 vb;
            vb.x = pack_bf16(b0.x, b0.y); vb.y = pack_bf16(b0.z, b0.w);
            vb.z = pack_bf16(b1v.x, b1v.y); vb.w = pack_bf16(b1v.z, b1v.w);
            *reinterpret_cast<uint4*>(&sB[off]) = vb;
        }
        __syncthreads();

#pragma unroll
        for (int kh = 0; kh < 2; kh++) {
            uint32_t bbr[4][4];
#pragma unroll
            for (int ni = 0; ni < 4; ni++) {
                int nrow = wn + ni * 8 + (lane & 7);
                int chunk = kh * 4 + ((lane >> 3) & 3);
                uint32_t addr = sBb + (uint32_t)(sw_off(nrow, chunk) * 2);
                ldsm4(bbr[ni][0], bbr[ni][1], bbr[ni][2], bbr[ni][3], addr);
            }
#pragma unroll
            for (int ks = 0; ks < 2; ks++) {
                uint32_t aa[4][4];
#pragma unroll
                for (int mi = 0; mi < 4; mi++) {
                    int row = wm + mi * 16 + (lane & 15);
                    int chunk = kh * 4 + ks * 2 + (lane >> 4);
                    uint32_t addr = sAb + (uint32_t)(sw_off(row, chunk) * 2);
                    ldsm4(aa[mi][0], aa[mi][1], aa[mi][2], aa[mi][3], addr);
                }
#pragma unroll
                for (int mi = 0; mi < 4; mi++)
#pragma unroll
                    for (int ni = 0; ni < 4; ni++)
                        mma16816(acc[mi][ni], aa[mi], &bbr[ni][ks * 2]);
            }
        }
    }

    // plain slice store (no atomics, no pre-zero needed)
    float* dst = g_hq4[ksp];
#pragma unroll
    for (int mi = 0; mi < 4; mi++) {
        int r0 = wm + mi * 16 + (lane >> 2);
#pragma unroll
        for (int ni = 0; ni < 4; ni++) {
            int col = n0 + wn + ni * 8 + ((lane & 3) << 1);
            float2 v0 = make_float2(acc[mi][ni][0], acc[mi][ni][1]);
            float2 v1 = make_float2(acc[mi][ni][2], acc[mi][ni][3]);
            *reinterpret_cast<float2*>(&dst[(size_t)(m0 + r0) * HID + col]) = v0;
            *reinterpret_cast<float2*>(&dst[(size_t)(m0 + r0 + 8) * HID + col]) = v1;
        }
    }
}

__global__ void __launch_bounds__(256, 2)
prep_kernel(const float* __restrict__ v, const float* __restrict__ q,
            const float* __restrict__ W1, const float* __restrict__ W2) {
    __shared__ __align__(16) __nv_bfloat16 sA[BMH * BKT];
    __shared__ __align__(16) __nv_bfloat16 sB[BMH * BKT];

    int bid = blockIdx.x;
    if (bid < HQ_BLK) {
        hq_body(bid, q, W1, sA, sB);
        return;
    }
    bid -= HQ_BLK;
    if (bid < NV_BLK) {
        size_t i = ((size_t)bid * 256 + threadIdx.x) * 8;
        float4 a = *reinterpret_cast<const float4*>(v + i);
        float4 b = *reinterpret_cast<const float4*>(v + i + 4);
        uint4 o;
        o.x = pack_bf16(a.x, a.y); o.y = pack_bf16(a.z, a.w);
        o.z = pack_bf16(b.x, b.y); o.w = pack_bf16(b.z, b.w);
        *reinterpret_cast<uint4*>(&g_vb[i]) = o;
        return;
    }
    bid -= NV_BLK;
    if (bid < NW_BLK) {
        size_t i = ((size_t)bid * 256 + threadIdx.x) * 8;
        if (i < (size_t)HID * VD) {
            size_t h = i >> 11;
            size_t k = i & 2047;
            const float* src = W1 + h * (VD + QD) + k;
            float4 a = *reinterpret_cast<const float4*>(src);
            float4 b = *reinterpret_cast<const float4*>(src + 4);
            uint4 o;
            o.x = pack_bf16(a.x, a.y); o.y = pack_bf16(a.z, a.w);
            o.z = pack_bf16(b.x, b.y); o.w = pack_bf16(b.z, b.w);
            *reinterpret_cast<uint4*>(&g_w1b[i]) = o;
        }
        return;
    }
    bid -= NW_BLK;
    if (bid < NORM1_BLK) {
        norm_partial(W1, HID * (VD + QD), 0, NORM1_BLK, bid);
        return;
    }
    bid -= NORM1_BLK;
    if (bid < NORM2_BLK) {
        norm_partial(W2, HID, 1, NORM2_BLK, bid);
        return;
    }
    bid -= NORM2_BLK;
    {
        int i = bid * 256 + threadIdx.x;
        for (int j = i; j < MROWS; j += ZERO_BLK * 256) g_logits[j] = 0.f;
    }
}

// ---------------------------------------------------------------------------
// reduce 4 hq slices -> g_hq  (3 MB, ~2.5us)
// ---------------------------------------------------------------------------
__global__ void hq_reduce_kernel() {
    size_t i = ((size_t)blockIdx.x * 256 + threadIdx.x) * 4;
    if (i >= (size_t)MQ * HID) return;
    float4 a = *reinterpret_cast<const float4*>(&g_hq4[0][i]);
    float4 b = *reinterpret_cast<const float4*>(&g_hq4[1][i]);
    float4 c = *reinterpret_cast<const float4*>(&g_hq4[2][i]);
    float4 d = *reinterpret_cast<const float4*>(&g_hq4[3][i]);
    float4 o;
    o.x = (a.x + b.x) + (c.x + d.x);
    o.y = (a.y + b.y) + (c.y + d.y);
    o.z = (a.z + b.z) + (c.z + d.z);
    o.w = (a.w + b.w) + (c.w + d.w);
    *reinterpret_cast<float4*>(&g_hq[i]) = o;
}

// ---------------------------------------------------------------------------
// Main GEMM (bf16, R8/R11 proven): TMA (SW128) 3-stage pipeline -> mma.sync,
// 256 threads, BM=128, BN=128, BK=64, 2 CTAs/SM.
// Fused epilogue relu(s1*(hv+hq)+b1).W2 -> atomicAdd.
// ---------------------------------------------------------------------------
#define STAGES 3
#define A_BYTES 16384                 // 128 x 64 bf16
#define B_BYTES 16384
#define STAGE_BYTES (A_BYTES + B_BYTES)
#define MAIN_KT (VD / 64)             // 32

__device__ __forceinline__ void mbar_init(uint32_t a, uint32_t cnt) {
    asm volatile("mbarrier.init.shared.b64 [%0], %1;" :: "r"(a), "r"(cnt) : "memory");
}
__device__ __forceinline__ void mbar_expect(uint32_t a, uint32_t bytes) {
    asm volatile("mbarrier.arrive.expect_tx.shared.b64 _, [%0], %1;"
                 :: "r"(a), "r"(bytes) : "memory");
}
__device__ __forceinline__ void mbar_wait(uint32_t a, uint32_t ph) {
    asm volatile(
        "{\n\t.reg .pred P;\n\t"
        "WAIT_%=:\n\t"
        "mbarrier.try_wait.parity.acquire.cta.shared::cta.b64 P, [%0], %1;\n\t"
        "@!P bra WAIT_%=;\n\t}"
        :: "r"(a), "r"(ph) : "memory");
}
__device__ __forceinline__ void tma2d(uint32_t dst, const CUtensorMap* m,
                                      int x, int y, uint32_t mbar) {
    asm volatile(
        "cp.async.bulk.tensor.2d.shared::cta.global.tile.mbarrier::complete_tx::bytes "
        "[%0], [%1, {%2, %3}], [%4];"
        :: "r"(dst), "l"(m), "r"(x), "r"(y), "r"(mbar) : "memory");
}

__global__ void __launch_bounds__(256, 2)
main_gemm_kernel(const __grid_constant__ CUtensorMap tmA,
                 const __grid_constant__ CUtensorMap tmB,
                 const float* __restrict__ b1, const float* __restrict__ W2,
                 const float* __restrict__ g1) {
    extern __shared__ __align__(16) char dsm[];
    uint32_t raw = (uint32_t)__cvta_generic_to_shared(dsm);
    uint32_t base = (raw + 1023u) & ~1023u;
    const uint32_t fullB = base + STAGES * STAGE_BYTES;

    const int tid = threadIdx.x;
    const int lane = tid & 31;
    const int wid = tid >> 5;
    const int nt = blockIdx.x & 7;      // 8 n-chunks of 128
    const int mt = blockIdx.x >> 3;     // 216 m-tiles
    const int m0 = mt * 128;
    const int n0 = nt * 128;
    const int wm = (wid >> 2) * 64;     // 2 m-warps
    const int wn = (wid & 3) * 32;      // 4 n-warps, 32 cols each

    if (tid == 0) {
        for (int s = 0; s < STAGES; s++) mbar_init(fullB + s * 8, 1);
        asm volatile("fence.proxy.async.shared::cta;" ::: "memory");
    }
    __syncthreads();

    if (tid == 0) {
#pragma unroll
        for (int s = 0; s < STAGES; s++) {
            mbar_expect(fullB + s * 8, STAGE_BYTES);
            tma2d(base + s * STAGE_BYTES, &tmA, s * 64, m0, fullB + s * 8);
            tma2d(base + s * STAGE_BYTES + A_BYTES, &tmB, s * 64, n0,
                  fullB + s * 8);
        }
    }

    float acc[4][4][4];
#pragma unroll
    for (int a = 0; a < 4; a++)
#pragma unroll
        for (int b = 0; b < 4; b++)
#pragma unroll
            for (int c = 0; c < 4; c++) acc[a][b][c] = 0.f;

    for (int kt = 0; kt < MAIN_KT; kt++) {
        const int r = kt / 3;
        const int s = kt - r * 3;
        mbar_wait(fullB + s * 8, r & 1);

        const uint32_t sa = base + s * STAGE_BYTES;
        const uint32_t sb = sa + A_BYTES;

#pragma unroll
        for (int kh = 0; kh < 2; kh++) {
            uint32_t bbr[4][4];
#pragma unroll
            for (int ni = 0; ni < 4; ni++) {
                int nrow = wn + ni * 8 + (lane & 7);
                int chunk = kh * 4 + ((lane >> 3) & 3);
                uint32_t addr = sb + (uint32_t)(sw_off(nrow, chunk) * 2);
                ldsm4(bbr[ni][0], bbr[ni][1], bbr[ni][2], bbr[ni][3], addr);
            }
#pragma unroll
            for (int ks = 0; ks < 2; ks++) {
                uint32_t aa[4][4];
#pragma unroll
                for (int mi = 0; mi < 4; mi++) {
                    int row = wm + mi * 16 + (lane & 15);
                    int chunk = kh * 4 + ks * 2 + (lane >> 4);
                    uint32_t addr = sa + (uint32_t)(sw_off(row, chunk) * 2);
                    ldsm4(aa[mi][0], aa[mi][1], aa[mi][2], aa[mi][3], addr);
                }
#pragma unroll
                for (int mi = 0; mi < 4; mi++)
#pragma unroll
                    for (int ni = 0; ni < 4; ni++)
                        mma16816(acc[mi][ni], aa[mi], &bbr[ni][ks * 2]);
            }
        }

        __syncthreads();
        if (tid == 0 && kt + STAGES < MAIN_KT) {
            mbar_expect(fullB + s * 8, STAGE_BYTES);
            tma2d(base + s * STAGE_BYTES, &tmA, (kt + STAGES) * 64, m0,
                  fullB + s * 8);
            tma2d(base + s * STAGE_BYTES + A_BYTES, &tmB, (kt + STAGES) * 64,
                  n0, fullB + s * 8);
        }
    }

    // ---------------- fused epilogue ----------------
    const float s1 = g1[0] * rsqrtf(g_norm2[0]);
#pragma unroll
    for (int mi = 0; mi < 4; mi++) {
        int r0 = wm + mi * 16 + (lane >> 2);
        int grow0 = m0 + r0;
        int grow1 = grow0 + 8;
        const float* hq0 = &g_hq[(size_t)(grow0 / NN) * HID];
        const float* hq1 = &g_hq[(size_t)(grow1 / NN) * HID];
        float sum0 = 0.f, sum1 = 0.f;
#pragma unroll
        for (int ni = 0; ni < 4; ni++) {
            int col = n0 + wn + ni * 8 + ((lane & 3) << 1);
#pragma unroll
            for (int j = 0; j < 2; j++) {
                float bb1 = b1[col + j];
                float ww2 = W2[col + j];
                float j0 = fmaxf(fmaf(s1, acc[mi][ni][j] + hq0[col + j], bb1), 0.f);
                float j1 = fmaxf(fmaf(s1, acc[mi][ni][2 + j] + hq1[col + j], bb1), 0.f);
                sum0 = fmaf(j0, ww2, sum0);
                sum1 = fmaf(j1, ww2, sum1);
            }
        }
        sum0 += __shfl_xor_sync(0xFFFFFFFFu, sum0, 1);
        sum0 += __shfl_xor_sync(0xFFFFFFFFu, sum0, 2);
        sum1 += __shfl_xor_sync(0xFFFFFFFFu, sum1, 1);
        sum1 += __shfl_xor_sync(0xFFFFFFFFu, sum1, 2);
        if ((lane & 3) == 0) {
            atomicAdd(&g_logits[grow0], sum0);
            atomicAdd(&g_logits[grow1], sum1);
        }
    }
}

// ---------------------------------------------------------------------------
__global__ void softmax_kernel(float* __restrict__ out,
                               const float* __restrict__ g2,
                               const float* __restrict__ b2) {
    int idx = blockIdx.x * blockDim.x + threadIdx.x;
    if (idx >= BB * NN) return;
    int b = idx / NN, n = idx % NN;
    float s2 = g2[0] * rsqrtf(g_norm2[1]);
    float b2v = b2[0];
    float vals[KK];
    float mx = -1e30f;
#pragma unroll
    for (int kk = 0; kk < KK; kk++) {
        float v = fmaf(s2, g_logits[(b * KK + kk) * NN + n], b2v);
        vals[kk] = v;
        mx = fmaxf(mx, v);
    }
    float sum = 0.f;
#pragma unroll
    for (int kk = 0; kk < KK; kk++) {
        vals[kk] = expf(vals[kk] - mx);
        sum += vals[kk];
    }
    float inv = 1.f / sum;
#pragma unroll
    for (int kk = 0; kk < KK; kk++)
        out[(b * KK + kk) * NN + n] = vals[kk] * inv;
}

// ---------------------------------------------------------------------------
typedef CUresult (*PFN_encodeTiled)(
    CUtensorMap*, CUtensorMapDataType, cuuint32_t, void*,
    const cuuint64_t*, const cuuint64_t*, const cuuint32_t*, const cuuint32_t*,
    CUtensorMapInterleave, CUtensorMapSwizzle, CUtensorMapL2promotion,
    CUtensorMapFloatOOBfill);

static void make_tm_bf16_2d(PFN_encodeTiled enc, CUtensorMap* tm, void* p,
                            uint64_t d0, uint64_t d1, uint32_t b0, uint32_t b1v) {
    cuuint64_t dims[2] = {d0, d1};
    cuuint64_t strides[1] = {d0 * 2};
    cuuint32_t box[2] = {b0, b1v};
    cuuint32_t es[2] = {1, 1};
    enc(tm, CU_TENSOR_MAP_DATA_TYPE_BFLOAT16, 2, p, dims, strides, box, es,
        CU_TENSOR_MAP_INTERLEAVE_NONE, CU_TENSOR_MAP_SWIZZLE_128B,
        CU_TENSOR_MAP_L2_PROMOTION_L2_128B, CU_TENSOR_MAP_FLOAT_OOB_FILL_NONE);
}

extern "C" void kernel_launch(void* const* d_in, const int* in_sizes, int n_in,
                              void* d_out, int out_size) {
    const float* v  = (const float*)d_in[0];
    const float* q  = (const float*)d_in[1];
    const float* W1 = (const float*)d_in[2];
    const float* g1 = (const float*)d_in[3];
    const float* b1 = (const float*)d_in[4];
    const float* W2 = (const float*)d_in[5];
    const float* g2 = (const float*)d_in[6];
    const float* b2 = (const float*)d_in[7];
    float* out = (float*)d_out;

    PFN_encodeTiled enc = nullptr;
    cudaDriverEntryPointQueryResult qres;
    cudaGetDriverEntryPoint("cuTensorMapEncodeTiled", (void**)&enc,
                            cudaEnableDefault, &qres);
    void *pv = nullptr, *pw = nullptr, *pn = nullptr;
    cudaGetSymbolAddress(&pv, g_vb);
    cudaGetSymbolAddress(&pw, g_w1b);
    cudaGetSymbolAddress(&pn, g_norm2);
    CUtensorMap tmA, tmB;
    make_tm_bf16_2d(enc, &tmA, pv, VD, MROWS, 64, 128);
    make_tm_bf16_2d(enc, &tmB, pw, VD, HID, 64, 128);

    const int SMEM_SZ = STAGES * STAGE_BYTES + 1024 + 128;
    cudaFuncSetAttribute(main_gemm_kernel,
                         cudaFuncAttributeMaxDynamicSharedMemorySize, SMEM_SZ);

    // reset norm accumulators via graph-capturable memset node
    cudaMemsetAsync(pn, 0, 2 * sizeof(float));

    // fused prep: hq slices (first, overlap) + converts + norms + zero logits
    prep_kernel<<<PREP_GRID, 256>>>(v, q, W1, W2);

    // reduce hq split-K slices
    hq_reduce_kernel<<<(MQ * HID / 4 + 255) / 256, 256>>>();

    // main fused GEMM (bf16): M=27648 (216 tiles), N=1024 (8 chunks), K=2048
    main_gemm_kernel<<<216 * 8, 256, SMEM_SZ>>>(tmA, tmB, b1, W2, g1);

    softmax_kernel<<<(BB * NN + 255) / 256, 256>>>(out, g2, b2);
}

// round 13
// speedup vs baseline: 1.1416x; 1.1416x over previous
#include <cuda_runtime.h>
#include <cuda.h>
#include <cuda_bf16.h>
#include <cstdint>

// Problem dims
#define VD   2048
#define QD   1024
#define HID  1024
#define BB   64
#define KK   12
#define NN   36
#define MROWS (BB*KK*NN)   // 27648
#define MQ    (BB*KK)      // 768

// ---------------- scratch (no cudaMalloc allowed) ----------------
__device__ float g_norm2[2];
__device__ int   g_hq_done;
__device__ float g_logits[MROWS];
__device__ float g_hq4[4][MQ * HID];                                // split-K slices
__device__ __align__(1024) __nv_bfloat16 g_vb[(size_t)MROWS * VD];  // 113 MB bf16 v
__device__ __align__(1024) __nv_bfloat16 g_w1b[(size_t)HID * VD];   // 4 MB bf16 W1[:, :VD]

// ---------------------------------------------------------------------------
__device__ __forceinline__ uint32_t pack_bf16(float x, float y) {
    __nv_bfloat162 h = __floats2bfloat162_rn(x, y);
    return *reinterpret_cast<uint32_t*>(&h);
}

// ---------------------------------------------------------------------------
// mma helpers
// ---------------------------------------------------------------------------
__device__ __forceinline__ void ldsm4(uint32_t& r0, uint32_t& r1, uint32_t& r2,
                                      uint32_t& r3, uint32_t addr) {
    asm volatile("ldmatrix.sync.aligned.m8n8.x4.shared.b16 {%0,%1,%2,%3}, [%4];"
                 : "=r"(r0), "=r"(r1), "=r"(r2), "=r"(r3)
                 : "r"(addr));
}

__device__ __forceinline__ void mma16816(float* c, const uint32_t* a,
                                         const uint32_t* b) {
    asm volatile(
        "mma.sync.aligned.m16n8k16.row.col.f32.bf16.bf16.f32 "
        "{%0,%1,%2,%3}, {%4,%5,%6,%7}, {%8,%9}, {%0,%1,%2,%3};"
        : "+f"(c[0]), "+f"(c[1]), "+f"(c[2]), "+f"(c[3])
        : "r"(a[0]), "r"(a[1]), "r"(a[2]), "r"(a[3]), "r"(b[0]), "r"(b[1]));
}

// swizzled elem offset in a [rows x 64] bf16 tile (128B rows, 16B chunks)
__device__ __forceinline__ int sw_off(int r, int c) {
    return r * 64 + ((c ^ (r & 7)) << 3);
}

// ---------------------------------------------------------------------------
// Fused prep kernel (R11 light version): block-role dispatch, low regs.
//   [0, NV)          : convert v -> bf16 (DRAM-bound long pole)
//   [+NV, +NW)       : convert W1[:, :VD] -> bf16
//   [+NW, +256)      : norm W1 (g_norm2 memset'd by graph node before this)
//   [+256, +260)     : norm W2
//   [+260, +388)     : zero g_logits
// ---------------------------------------------------------------------------
#define NV_BLK (MROWS * VD / 8 / 256)       // 27648
#define NW_BLK (HID * VD / 8 / 256)         // 1024
#define NORM1_BLK 256
#define NORM2_BLK 4
#define ZERO_BLK 128
#define PREP_GRID (NV_BLK + NW_BLK + NORM1_BLK + NORM2_BLK + ZERO_BLK)

__device__ __forceinline__ void norm_partial(const float* __restrict__ p,
                                             int n, int slot, int nblocks,
                                             int bid) {
    float s = 0.f;
    for (int i = bid * 256 + threadIdx.x; i < n; i += nblocks * 256) {
        float v = p[i];
        s += v * v;
    }
    for (int o = 16; o; o >>= 1) s += __shfl_xor_sync(0xFFFFFFFFu, s, o);
    __shared__ float sh[8];
    int lane = threadIdx.x & 31, w = threadIdx.x >> 5;
    if (!lane) sh[w] = s;
    __syncthreads();
    if (!w) {
        s = (lane < 8) ? sh[lane] : 0.f;
        for (int o = 4; o; o >>= 1) s += __shfl_xor_sync(0xFFFFFFFFu, s, o);
        if (!lane) atomicAdd(&g_norm2[slot], s);
    }
}

__global__ void prep_kernel(const float* __restrict__ v,
                            const float* __restrict__ W1,
                            const float* __restrict__ W2) {
    int bid = blockIdx.x;
    if (bid < NV_BLK) {
        size_t i = ((size_t)bid * 256 + threadIdx.x) * 8;
        float4 a = *reinterpret_cast<const float4*>(v + i);
        float4 b = *reinterpret_cast<const float4*>(v + i + 4);
        uint4 o;
        o.x = pack_bf16(a.x, a.y); o.y = pack_bf16(a.z, a.w);
        o.z = pack_bf16(b.x, b.y); o.w = pack_bf16(b.z, b.w);
        *reinterpret_cast<uint4*>(&g_vb[i]) = o;
        return;
    }
    bid -= NV_BLK;
    if (bid < NW_BLK) {
        size_t i = ((size_t)bid * 256 + threadIdx.x) * 8;
        if (i < (size_t)HID * VD) {
            size_t h = i >> 11;
            size_t k = i & 2047;
            const float* src = W1 + h * (VD + QD) + k;
            float4 a = *reinterpret_cast<const float4*>(src);
            float4 b = *reinterpret_cast<const float4*>(src + 4);
            uint4 o;
            o.x = pack_bf16(a.x, a.y); o.y = pack_bf16(a.z, a.w);
            o.z = pack_bf16(b.x, b.y); o.w = pack_bf16(b.z, b.w);
            *reinterpret_cast<uint4*>(&g_w1b[i]) = o;
        }
        return;
    }
    bid -= NW_BLK;
    if (bid < NORM1_BLK) {
        norm_partial(W1, HID * (VD + QD), 0, NORM1_BLK, bid);
        return;
    }
    bid -= NORM1_BLK;
    if (bid < NORM2_BLK) {
        norm_partial(W2, HID, 1, NORM2_BLK, bid);
        return;
    }
    bid -= NORM2_BLK;
    {
        int i = bid * 256 + threadIdx.x;
        for (int j = i; j < MROWS; j += ZERO_BLK * 256) g_logits[j] = 0.f;
    }
}

// ---------------------------------------------------------------------------
// Main GEMM kernel: 192 hq blocks (first) + 1728 main tiles.
// hq: 128x128x256 slice per block -> g_hq4[ksp], then signal g_hq_done.
// main: TMA (SW128) 3-stage pipeline -> mma.sync bf16, BM=BN=128, BK=64,
//       2 CTAs/SM; epilogue acquire-spins on g_hq_done, sums 4 hq slices,
//       relu(s1*(hv+hq)+b1).W2 -> atomicAdd(g_logits).
// ---------------------------------------------------------------------------
#define HQ_BLK 192
#define BMH 128
#define BKT 64
#define STAGES 3
#define A_BYTES 16384                 // 128 x 64 bf16
#define B_BYTES 16384
#define STAGE_BYTES (A_BYTES + B_BYTES)
#define MAIN_KT (VD / 64)             // 32

__device__ __forceinline__ void mbar_init(uint32_t a, uint32_t cnt) {
    asm volatile("mbarrier.init.shared.b64 [%0], %1;" :: "r"(a), "r"(cnt) : "memory");
}
__device__ __forceinline__ void mbar_expect(uint32_t a, uint32_t bytes) {
    asm volatile("mbarrier.arrive.expect_tx.shared.b64 _, [%0], %1;"
                 :: "r"(a), "r"(bytes) : "memory");
}
__device__ __forceinline__ void mbar_wait(uint32_t a, uint32_t ph) {
    asm volatile(
        "{\n\t.reg .pred P;\n\t"
        "WAIT_%=:\n\t"
        "mbarrier.try_wait.parity.acquire.cta.shared::cta.b64 P, [%0], %1;\n\t"
        "@!P bra WAIT_%=;\n\t}"
        :: "r"(a), "r"(ph) : "memory");
}
__device__ __forceinline__ void tma2d(uint32_t dst, const CUtensorMap* m,
                                      int x, int y, uint32_t mbar) {
    asm volatile(
        "cp.async.bulk.tensor.2d.shared::cta.global.tile.mbarrier::complete_tx::bytes "
        "[%0], [%1, {%2, %3}], [%4];"
        :: "r"(dst), "l"(m), "r"(x), "r"(y), "r"(mbar) : "memory");
}

// hq GEMM slice body (runs inside main kernel; smem passed in)
__device__ void hq_body(int bid, const float* __restrict__ q,
                        const float* __restrict__ W1,
                        __nv_bfloat16* sA, __nv_bfloat16* sB) {
    const int tid = threadIdx.x;
    const int lane = tid & 31;
    const int wid = tid >> 5;
    const int nt = bid & 7;
    const int rest = bid >> 3;        // 0..23
    const int mt = rest % 6;
    const int ksp = rest / 6;         // 0..3
    const int m0 = mt * BMH;
    const int n0 = nt * BMH;
    const int wm = (wid >> 2) * 64;
    const int wn = (wid & 3) * 32;
    const int kbase = ksp * 256;
    const int KT = 256 / BKT;         // 4

    const float* Ag = q + kbase;
    const int kofs = VD + kbase;

    float acc[4][4][4];
#pragma unroll
    for (int a = 0; a < 4; a++)
#pragma unroll
        for (int b = 0; b < 4; b++)
#pragma unroll
            for (int c = 0; c < 4; c++) acc[a][b][c] = 0.f;

    int lr[4], lc[4];
#pragma unroll
    for (int i = 0; i < 4; i++) {
        int ch = tid + i * 256;
        lr[i] = ch >> 3;
        lc[i] = ch & 7;
    }

    const uint32_t sAb = (uint32_t)__cvta_generic_to_shared(sA);
    const uint32_t sBb = (uint32_t)__cvta_generic_to_shared(sB);

    for (int kt = 0; kt < KT; kt++) {
        __syncthreads();
        int k0 = kt * BKT;
#pragma unroll
        for (int i = 0; i < 4; i++) {
            const float4* ap = reinterpret_cast<const float4*>(
                Ag + (size_t)(m0 + lr[i]) * QD + k0 + lc[i] * 8);
            float4 a0 = ap[0], a1 = ap[1];
            const float4* bp = reinterpret_cast<const float4*>(
                W1 + (size_t)(n0 + lr[i]) * (VD + QD) + kofs + k0 + lc[i] * 8);
            float4 b0 = bp[0], b1v = bp[1];
            int off = sw_off(lr[i], lc[i]);
            uint4 va;
            va.x = pack_bf16(a0.x, a0.y); va.y = pack_bf16(a0.z, a0.w);
            va.z = pack_bf16(a1.x, a1.y); va.w = pack_bf16(a1.z, a1.w);
            *reinterpret_cast<uint4*>(&sA[off]) = va;
            uint4 vb;
            vb.x = pack_bf16(b0.x, b0.y); vb.y = pack_bf16(b0.z, b0.w);
            vb.z = pack_bf16(b1v.x, b1v.y); vb.w = pack_bf16(b1v.z, b1v.w);
            *reinterpret_cast<uint4*>(&sB[off]) = vb;
        }
        __syncthreads();

#pragma unroll
        for (int kh = 0; kh < 2; kh++) {
            uint32_t bbr[4][4];
#pragma unroll
            for (int ni = 0; ni < 4; ni++) {
                int nrow = wn + ni * 8 + (lane & 7);
                int chunk = kh * 4 + ((lane >> 3) & 3);
                uint32_t addr = sBb + (uint32_t)(sw_off(nrow, chunk) * 2);
                ldsm4(bbr[ni][0], bbr[ni][1], bbr[ni][2], bbr[ni][3], addr);
            }
#pragma unroll
            for (int ks = 0; ks < 2; ks++) {
                uint32_t aa[4][4];
#pragma unroll
                for (int mi = 0; mi < 4; mi++) {
                    int row = wm + mi * 16 + (lane & 15);
                    int chunk = kh * 4 + ks * 2 + (lane >> 4);
                    uint32_t addr = sAb + (uint32_t)(sw_off(row, chunk) * 2);
                    ldsm4(aa[mi][0], aa[mi][1], aa[mi][2], aa[mi][3], addr);
                }
#pragma unroll
                for (int mi = 0; mi < 4; mi++)
#pragma unroll
                    for (int ni = 0; ni < 4; ni++)
                        mma16816(acc[mi][ni], aa[mi], &bbr[ni][ks * 2]);
            }
        }
    }

    // plain slice store (no atomics)
    float* dst = g_hq4[ksp];
#pragma unroll
    for (int mi = 0; mi < 4; mi++) {
        int r0 = wm + mi * 16 + (lane >> 2);
#pragma unroll
        for (int ni = 0; ni < 4; ni++) {
            int col = n0 + wn + ni * 8 + ((lane & 3) << 1);
            float2 v0 = make_float2(acc[mi][ni][0], acc[mi][ni][1]);
            float2 v1 = make_float2(acc[mi][ni][2], acc[mi][ni][3]);
            *reinterpret_cast<float2*>(&dst[(size_t)(m0 + r0) * HID + col]) = v0;
            *reinterpret_cast<float2*>(&dst[(size_t)(m0 + r0 + 8) * HID + col]) = v1;
        }
    }

    // publish: all stores visible, then count this block done
    __threadfence();
    __syncthreads();
    if (tid == 0) atomicAdd(&g_hq_done, 1);
}

__global__ void __launch_bounds__(256, 2)
main_gemm_kernel(const __grid_constant__ CUtensorMap tmA,
                 const __grid_constant__ CUtensorMap tmB,
                 const float* __restrict__ q, const float* __restrict__ W1,
                 const float* __restrict__ b1, const float* __restrict__ W2,
                 const float* __restrict__ g1) {
    extern __shared__ __align__(16) char dsm[];
    uint32_t raw = (uint32_t)__cvta_generic_to_shared(dsm);
    uint32_t base = (raw + 1023u) & ~1023u;

    if (blockIdx.x < HQ_BLK) {
        // offset hq tiles into the aligned smem region
        __nv_bfloat16* sA = reinterpret_cast<__nv_bfloat16*>(
            dsm + (base - raw));
        hq_body(blockIdx.x, q, W1, sA, sA + BMH * BKT);
        return;
    }

    const uint32_t fullB = base + STAGES * STAGE_BYTES;
    const int bid = blockIdx.x - HQ_BLK;
    const int tid = threadIdx.x;
    const int lane = tid & 31;
    const int wid = tid >> 5;
    const int nt = bid & 7;      // 8 n-chunks of 128
    const int mt = bid >> 3;     // 216 m-tiles
    const int m0 = mt * 128;
    const int n0 = nt * 128;
    const int wm = (wid >> 2) * 64;     // 2 m-warps
    const int wn = (wid & 3) * 32;      // 4 n-warps, 32 cols each

    if (tid == 0) {
        for (int s = 0; s < STAGES; s++) mbar_init(fullB + s * 8, 1);
        asm volatile("fence.proxy.async.shared::cta;" ::: "memory");
    }
    __syncthreads();

    if (tid == 0) {
#pragma unroll
        for (int s = 0; s < STAGES; s++) {
            mbar_expect(fullB + s * 8, STAGE_BYTES);
            tma2d(base + s * STAGE_BYTES, &tmA, s * 64, m0, fullB + s * 8);
            tma2d(base + s * STAGE_BYTES + A_BYTES, &tmB, s * 64, n0,
                  fullB + s * 8);
        }
    }

    float acc[4][4][4];
#pragma unroll
    for (int a = 0; a < 4; a++)
#pragma unroll
        for (int b = 0; b < 4; b++)
#pragma unroll
            for (int c = 0; c < 4; c++) acc[a][b][c] = 0.f;

    for (int kt = 0; kt < MAIN_KT; kt++) {
        const int r = kt / 3;
        const int s = kt - r * 3;
        mbar_wait(fullB + s * 8, r & 1);

        const uint32_t sa = base + s * STAGE_BYTES;
        const uint32_t sb = sa + A_BYTES;

#pragma unroll
        for (int kh = 0; kh < 2; kh++) {
            uint32_t bbr[4][4];
#pragma unroll
            for (int ni = 0; ni < 4; ni++) {
                int nrow = wn + ni * 8 + (lane & 7);
                int chunk = kh * 4 + ((lane >> 3) & 3);
                uint32_t addr = sb + (uint32_t)(sw_off(nrow, chunk) * 2);
                ldsm4(bbr[ni][0], bbr[ni][1], bbr[ni][2], bbr[ni][3], addr);
            }
#pragma unroll
            for (int ks = 0; ks < 2; ks++) {
                uint32_t aa[4][4];
#pragma unroll
                for (int mi = 0; mi < 4; mi++) {
                    int row = wm + mi * 16 + (lane & 15);
                    int chunk = kh * 4 + ks * 2 + (lane >> 4);
                    uint32_t addr = sa + (uint32_t)(sw_off(row, chunk) * 2);
                    ldsm4(aa[mi][0], aa[mi][1], aa[mi][2], aa[mi][3], addr);
                }
#pragma unroll
                for (int mi = 0; mi < 4; mi++)
#pragma unroll
                    for (int ni = 0; ni < 4; ni++)
                        mma16816(acc[mi][ni], aa[mi], &bbr[ni][ks * 2]);
            }
        }

        __syncthreads();
        if (tid == 0 && kt + STAGES < MAIN_KT) {
            mbar_expect(fullB + s * 8, STAGE_BYTES);
            tma2d(base + s * STAGE_BYTES, &tmA, (kt + STAGES) * 64, m0,
                  fullB + s * 8);
            tma2d(base + s * STAGE_BYTES + A_BYTES, &tmB, (kt + STAGES) * 64,
                  n0, fullB + s * 8);
        }
    }

    // ---------------- wait for hq slices (normally already done) ----------
    {
        int done;
        do {
            asm volatile("ld.global.acquire.gpu.b32 %0, [%1];"
                         : "=r"(done) : "l"(&g_hq_done) : "memory");
        } while (done < HQ_BLK);
    }

    // ---------------- fused epilogue ----------------
    const float s1 = g1[0] * rsqrtf(g_norm2[0]);
#pragma unroll
    for (int mi = 0; mi < 4; mi++) {
        int r0 = wm + mi * 16 + (lane >> 2);
        int grow0 = m0 + r0;
        int grow1 = grow0 + 8;
        size_t hb0 = (size_t)(grow0 / NN) * HID;
        size_t hb1 = (size_t)(grow1 / NN) * HID;
        float sum0 = 0.f, sum1 = 0.f;
#pragma unroll
        for (int ni = 0; ni < 4; ni++) {
            int col = n0 + wn + ni * 8 + ((lane & 3) << 1);
#pragma unroll
            for (int j = 0; j < 2; j++) {
                float bb1 = b1[col + j];
                float ww2 = W2[col + j];
                float h0 = (g_hq4[0][hb0 + col + j] + g_hq4[1][hb0 + col + j]) +
                           (g_hq4[2][hb0 + col + j] + g_hq4[3][hb0 + col + j]);
                float h1 = (g_hq4[0][hb1 + col + j] + g_hq4[1][hb1 + col + j]) +
                           (g_hq4[2][hb1 + col + j] + g_hq4[3][hb1 + col + j]);
                float j0 = fmaxf(fmaf(s1, acc[mi][ni][j] + h0, bb1), 0.f);
                float j1 = fmaxf(fmaf(s1, acc[mi][ni][2 + j] + h1, bb1), 0.f);
                sum0 = fmaf(j0, ww2, sum0);
                sum1 = fmaf(j1, ww2, sum1);
            }
        }
        sum0 += __shfl_xor_sync(0xFFFFFFFFu, sum0, 1);
        sum0 += __shfl_xor_sync(0xFFFFFFFFu, sum0, 2);
        sum1 += __shfl_xor_sync(0xFFFFFFFFu, sum1, 1);
        sum1 += __shfl_xor_sync(0xFFFFFFFFu, sum1, 2);
        if ((lane & 3) == 0) {
            atomicAdd(&g_logits[grow0], sum0);
            atomicAdd(&g_logits[grow1], sum1);
        }
    }
}

// ---------------------------------------------------------------------------
__global__ void softmax_kernel(float* __restrict__ out,
                               const float* __restrict__ g2,
                               const float* __restrict__ b2) {
    int idx = blockIdx.x * blockDim.x + threadIdx.x;
    if (idx >= BB * NN) return;
    int b = idx / NN, n = idx % NN;
    float s2 = g2[0] * rsqrtf(g_norm2[1]);
    float b2v = b2[0];
    float vals[KK];
    float mx = -1e30f;
#pragma unroll
    for (int kk = 0; kk < KK; kk++) {
        float v = fmaf(s2, g_logits[(b * KK + kk) * NN + n], b2v);
        vals[kk] = v;
        mx = fmaxf(mx, v);
    }
    float sum = 0.f;
#pragma unroll
    for (int kk = 0; kk < KK; kk++) {
        vals[kk] = expf(vals[kk] - mx);
        sum += vals[kk];
    }
    float inv = 1.f / sum;
#pragma unroll
    for (int kk = 0; kk < KK; kk++)
        out[(b * KK + kk) * NN + n] = vals[kk] * inv;
}

// ---------------------------------------------------------------------------
typedef CUresult (*PFN_encodeTiled)(
    CUtensorMap*, CUtensorMapDataType, cuuint32_t, void*,
    const cuuint64_t*, const cuuint64_t*, const cuuint32_t*, const cuuint32_t*,
    CUtensorMapInterleave, CUtensorMapSwizzle, CUtensorMapL2promotion,
    CUtensorMapFloatOOBfill);

static void make_tm_bf16_2d(PFN_encodeTiled enc, CUtensorMap* tm, void* p,
                            uint64_t d0, uint64_t d1, uint32_t b0, uint32_t b1v) {
    cuuint64_t dims[2] = {d0, d1};
    cuuint64_t strides[1] = {d0 * 2};
    cuuint32_t box[2] = {b0, b1v};
    cuuint32_t es[2] = {1, 1};
    enc(tm, CU_TENSOR_MAP_DATA_TYPE_BFLOAT16, 2, p, dims, strides, box, es,
        CU_TENSOR_MAP_INTERLEAVE_NONE, CU_TENSOR_MAP_SWIZZLE_128B,
        CU_TENSOR_MAP_L2_PROMOTION_L2_128B, CU_TENSOR_MAP_FLOAT_OOB_FILL_NONE);
}

extern "C" void kernel_launch(void* const* d_in, const int* in_sizes, int n_in,
                              void* d_out, int out_size) {
    const float* v  = (const float*)d_in[0];
    const float* q  = (const float*)d_in[1];
    const float* W1 = (const float*)d_in[2];
    const float* g1 = (const float*)d_in[3];
    const float* b1 = (const float*)d_in[4];
    const float* W2 = (const float*)d_in[5];
    const float* g2 = (const float*)d_in[6];
    const float* b2 = (const float*)d_in[7];
    float* out = (float*)d_out;

    PFN_encodeTiled enc = nullptr;
    cudaDriverEntryPointQueryResult qres;
    cudaGetDriverEntryPoint("cuTensorMapEncodeTiled", (void**)&enc,
                            cudaEnableDefault, &qres);
    void *pv = nullptr, *pw = nullptr, *pn = nullptr, *pd = nullptr;
    cudaGetSymbolAddress(&pv, g_vb);
    cudaGetSymbolAddress(&pw, g_w1b);
    cudaGetSymbolAddress(&pn, g_norm2);
    cudaGetSymbolAddress(&pd, g_hq_done);
    CUtensorMap tmA, tmB;
    make_tm_bf16_2d(enc, &tmA, pv, VD, MROWS, 64, 128);
    make_tm_bf16_2d(enc, &tmB, pw, VD, HID, 64, 128);

    const int SMEM_SZ = STAGES * STAGE_BYTES + 1024 + 128;
    cudaFuncSetAttribute(main_gemm_kernel,
                         cudaFuncAttributeMaxDynamicSharedMemorySize, SMEM_SZ);

    // reset accumulators via graph-capturable memset nodes
    cudaMemsetAsync(pn, 0, 2 * sizeof(float));
    cudaMemsetAsync(pd, 0, sizeof(int));

    // prep (light regs): converts + norms + zero logits
    prep_kernel<<<PREP_GRID, 256>>>(v, W1, W2);

    // main: 192 hq blocks (overlap with main mainloop) + 1728 main tiles
    main_gemm_kernel<<<HQ_BLK + 216 * 8, 256, SMEM_SZ>>>(
        tmA, tmB, q, W1, b1, W2, g1);

    softmax_kernel<<<(BB * NN + 255) / 256, 256>>>(out, g2, b2);
}

// round 14
// speedup vs baseline: 1.1807x; 1.0343x over previous
#include <cuda_runtime.h>
#include <cuda.h>
#include <cuda_bf16.h>
#include <cstdint>

// Problem dims
#define VD   2048
#define QD   1024
#define HID  1024
#define BB   64
#define KK   12
#define NN   36
#define MROWS (BB*KK*NN)   // 27648
#define MQ    (BB*KK)      // 768

// ---------------- scratch (no cudaMalloc allowed) ----------------
__device__ float g_norm2[2];
__device__ int   g_hq_done;
__device__ float g_logits[MROWS];
__device__ float g_hq4[4][MQ * HID];                                // split-K slices
__device__ __align__(1024) __nv_bfloat16 g_vb[(size_t)MROWS * VD];  // 113 MB bf16 v
__device__ __align__(1024) __nv_bfloat16 g_w1b[(size_t)HID * VD];   // 4 MB bf16 W1[:, :VD]

// ---------------------------------------------------------------------------
__device__ __forceinline__ uint32_t pack_bf16(float x, float y) {
    __nv_bfloat162 h = __floats2bfloat162_rn(x, y);
    return *reinterpret_cast<uint32_t*>(&h);
}

// ---------------------------------------------------------------------------
// mma helpers
// ---------------------------------------------------------------------------
__device__ __forceinline__ void ldsm4(uint32_t& r0, uint32_t& r1, uint32_t& r2,
                                      uint32_t& r3, uint32_t addr) {
    asm volatile("ldmatrix.sync.aligned.m8n8.x4.shared.b16 {%0,%1,%2,%3}, [%4];"
                 : "=r"(r0), "=r"(r1), "=r"(r2), "=r"(r3)
                 : "r"(addr));
}

__device__ __forceinline__ void mma16816(float* c, const uint32_t* a,
                                         const uint32_t* b) {
    asm volatile(
        "mma.sync.aligned.m16n8k16.row.col.f32.bf16.bf16.f32 "
        "{%0,%1,%2,%3}, {%4,%5,%6,%7}, {%8,%9}, {%0,%1,%2,%3};"
        : "+f"(c[0]), "+f"(c[1]), "+f"(c[2]), "+f"(c[3])
        : "r"(a[0]), "r"(a[1]), "r"(a[2]), "r"(a[3]), "r"(b[0]), "r"(b[1]));
}

// swizzled elem offset in a [rows x 64] bf16 tile (128B rows, 16B chunks)
__device__ __forceinline__ int sw_off(int r, int c) {
    return r * 64 + ((c ^ (r & 7)) << 3);
}

// ---------------------------------------------------------------------------
// Fused prep kernel (light regs): block-role dispatch.
//   [0, NV)          : convert v -> bf16 (DRAM-bound long pole)
//   [+NV, +NW)       : convert W1[:, :VD] -> bf16
//   [+NW, +256)      : norm W1 (g_norm2 memset'd by graph node before this)
//   [+256, +260)     : norm W2
//   [+260, +388)     : zero g_logits
// ---------------------------------------------------------------------------
#define NV_BLK (MROWS * VD / 8 / 256)       // 27648
#define NW_BLK (HID * VD / 8 / 256)         // 1024
#define NORM1_BLK 256
#define NORM2_BLK 4
#define ZERO_BLK 128
#define PREP_GRID (NV_BLK + NW_BLK + NORM1_BLK + NORM2_BLK + ZERO_BLK)

__device__ __forceinline__ void norm_partial(const float* __restrict__ p,
                                             int n, int slot, int nblocks,
                                             int bid) {
    float s = 0.f;
    for (int i = bid * 256 + threadIdx.x; i < n; i += nblocks * 256) {
        float v = p[i];
        s += v * v;
    }
    for (int o = 16; o; o >>= 1) s += __shfl_xor_sync(0xFFFFFFFFu, s, o);
    __shared__ float sh[8];
    int lane = threadIdx.x & 31, w = threadIdx.x >> 5;
    if (!lane) sh[w] = s;
    __syncthreads();
    if (!w) {
        s = (lane < 8) ? sh[lane] : 0.f;
        for (int o = 4; o; o >>= 1) s += __shfl_xor_sync(0xFFFFFFFFu, s, o);
        if (!lane) atomicAdd(&g_norm2[slot], s);
    }
}

__global__ void prep_kernel(const float* __restrict__ v,
                            const float* __restrict__ W1,
                            const float* __restrict__ W2) {
    int bid = blockIdx.x;
    if (bid < NV_BLK) {
        size_t i = ((size_t)bid * 256 + threadIdx.x) * 8;
        float4 a = *reinterpret_cast<const float4*>(v + i);
        float4 b = *reinterpret_cast<const float4*>(v + i + 4);
        uint4 o;
        o.x = pack_bf16(a.x, a.y); o.y = pack_bf16(a.z, a.w);
        o.z = pack_bf16(b.x, b.y); o.w = pack_bf16(b.z, b.w);
        *reinterpret_cast<uint4*>(&g_vb[i]) = o;
        return;
    }
    bid -= NV_BLK;
    if (bid < NW_BLK) {
        size_t i = ((size_t)bid * 256 + threadIdx.x) * 8;
        if (i < (size_t)HID * VD) {
            size_t h = i >> 11;
            size_t k = i & 2047;
            const float* src = W1 + h * (VD + QD) + k;
            float4 a = *reinterpret_cast<const float4*>(src);
            float4 b = *reinterpret_cast<const float4*>(src + 4);
            uint4 o;
            o.x = pack_bf16(a.x, a.y); o.y = pack_bf16(a.z, a.w);
            o.z = pack_bf16(b.x, b.y); o.w = pack_bf16(b.z, b.w);
            *reinterpret_cast<uint4*>(&g_w1b[i]) = o;
        }
        return;
    }
    bid -= NW_BLK;
    if (bid < NORM1_BLK) {
        norm_partial(W1, HID * (VD + QD), 0, NORM1_BLK, bid);
        return;
    }
    bid -= NORM1_BLK;
    if (bid < NORM2_BLK) {
        norm_partial(W2, HID, 1, NORM2_BLK, bid);
        return;
    }
    bid -= NORM2_BLK;
    {
        int i = bid * 256 + threadIdx.x;
        for (int j = i; j < MROWS; j += ZERO_BLK * 256) g_logits[j] = 0.f;
    }
}

// ---------------------------------------------------------------------------
// Main GEMM kernel: 192 hq blocks (first) + 1728 main tiles.
// hq: 128x128x256 slice per block -> g_hq4[ksp], then signal g_hq_done.
// main: TMA (SW128) 3-stage pipeline -> mma.sync bf16, BM=BN=128, BK=64,
//       2 CTAs/SM; after mainloop: spin on g_hq_done, cooperatively reduce
//       the <=5 needed hq rows x 128 cols into smem (slice sum), then
//       relu(s1*(hv+hq)+b1).W2 -> atomicAdd(g_logits).
// ---------------------------------------------------------------------------
#define HQ_BLK 192
#define BMH 128
#define BKT 64
#define STAGES 3
#define A_BYTES 16384                 // 128 x 64 bf16
#define B_BYTES 16384
#define STAGE_BYTES (A_BYTES + B_BYTES)
#define MAIN_KT (VD / 64)             // 32

__device__ __forceinline__ void mbar_init(uint32_t a, uint32_t cnt) {
    asm volatile("mbarrier.init.shared.b64 [%0], %1;" :: "r"(a), "r"(cnt) : "memory");
}
__device__ __forceinline__ void mbar_expect(uint32_t a, uint32_t bytes) {
    asm volatile("mbarrier.arrive.expect_tx.shared.b64 _, [%0], %1;"
                 :: "r"(a), "r"(bytes) : "memory");
}
__device__ __forceinline__ void mbar_wait(uint32_t a, uint32_t ph) {
    asm volatile(
        "{\n\t.reg .pred P;\n\t"
        "WAIT_%=:\n\t"
        "mbarrier.try_wait.parity.acquire.cta.shared::cta.b64 P, [%0], %1;\n\t"
        "@!P bra WAIT_%=;\n\t}"
        :: "r"(a), "r"(ph) : "memory");
}
__device__ __forceinline__ void tma2d(uint32_t dst, const CUtensorMap* m,
                                      int x, int y, uint32_t mbar) {
    asm volatile(
        "cp.async.bulk.tensor.2d.shared::cta.global.tile.mbarrier::complete_tx::bytes "
        "[%0], [%1, {%2, %3}], [%4];"
        :: "r"(dst), "l"(m), "r"(x), "r"(y), "r"(mbar) : "memory");
}

// hq GEMM slice body (runs inside main kernel; smem passed in)
__device__ void hq_body(int bid, const float* __restrict__ q,
                        const float* __restrict__ W1,
                        __nv_bfloat16* sA, __nv_bfloat16* sB) {
    const int tid = threadIdx.x;
    const int lane = tid & 31;
    const int wid = tid >> 5;
    const int nt = bid & 7;
    const int rest = bid >> 3;        // 0..23
    const int mt = rest % 6;
    const int ksp = rest / 6;         // 0..3
    const int m0 = mt * BMH;
    const int n0 = nt * BMH;
    const int wm = (wid >> 2) * 64;
    const int wn = (wid & 3) * 32;
    const int kbase = ksp * 256;
    const int KT = 256 / BKT;         // 4

    const float* Ag = q + kbase;
    const int kofs = VD + kbase;

    float acc[4][4][4];
#pragma unroll
    for (int a = 0; a < 4; a++)
#pragma unroll
        for (int b = 0; b < 4; b++)
#pragma unroll
            for (int c = 0; c < 4; c++) acc[a][b][c] = 0.f;

    int lr[4], lc[4];
#pragma unroll
    for (int i = 0; i < 4; i++) {
        int ch = tid + i * 256;
        lr[i] = ch >> 3;
        lc[i] = ch & 7;
    }

    const uint32_t sAb = (uint32_t)__cvta_generic_to_shared(sA);
    const uint32_t sBb = (uint32_t)__cvta_generic_to_shared(sB);

    for (int kt = 0; kt < KT; kt++) {
        __syncthreads();
        int k0 = kt * BKT;
#pragma unroll
        for (int i = 0; i < 4; i++) {
            const float4* ap = reinterpret_cast<const float4*>(
                Ag + (size_t)(m0 + lr[i]) * QD + k0 + lc[i] * 8);
            float4 a0 = ap[0], a1 = ap[1];
            const float4* bp = reinterpret_cast<const float4*>(
                W1 + (size_t)(n0 + lr[i]) * (VD + QD) + kofs + k0 + lc[i] * 8);
            float4 b0 = bp[0], b1v = bp[1];
            int off = sw_off(lr[i], lc[i]);
            uint4 va;
            va.x = pack_bf16(a0.x, a0.y); va.y = pack_bf16(a0.z, a0.w);
            va.z = pack_bf16(a1.x, a1.y); va.w = pack_bf16(a1.z, a1.w);
            *reinterpret_cast<uint4*>(&sA[off]) = va;
            uint4 vb;
            vb.x = pack_bf16(b0.x, b0.y); vb.y = pack_bf16(b0.z, b0.w);
            vb.z = pack_bf16(b1v.x, b1v.y); vb.w = pack_bf16(b1v.z, b1v.w);
            *reinterpret_cast<uint4*>(&sB[off]) = vb;
        }
        __syncthreads();

#pragma unroll
        for (int kh = 0; kh < 2; kh++) {
            uint32_t bbr[4][4];
#pragma unroll
            for (int ni = 0; ni < 4; ni++) {
                int nrow = wn + ni * 8 + (lane & 7);
                int chunk = kh * 4 + ((lane >> 3) & 3);
                uint32_t addr = sBb + (uint32_t)(sw_off(nrow, chunk) * 2);
                ldsm4(bbr[ni][0], bbr[ni][1], bbr[ni][2], bbr[ni][3], addr);
            }
#pragma unroll
            for (int ks = 0; ks < 2; ks++) {
                uint32_t aa[4][4];
#pragma unroll
                for (int mi = 0; mi < 4; mi++) {
                    int row = wm + mi * 16 + (lane & 15);
                    int chunk = kh * 4 + ks * 2 + (lane >> 4);
                    uint32_t addr = sAb + (uint32_t)(sw_off(row, chunk) * 2);
                    ldsm4(aa[mi][0], aa[mi][1], aa[mi][2], aa[mi][3], addr);
                }
#pragma unroll
                for (int mi = 0; mi < 4; mi++)
#pragma unroll
                    for (int ni = 0; ni < 4; ni++)
                        mma16816(acc[mi][ni], aa[mi], &bbr[ni][ks * 2]);
            }
        }
    }

    // plain slice store (no atomics)
    float* dst = g_hq4[ksp];
#pragma unroll
    for (int mi = 0; mi < 4; mi++) {
        int r0 = wm + mi * 16 + (lane >> 2);
#pragma unroll
        for (int ni = 0; ni < 4; ni++) {
            int col = n0 + wn + ni * 8 + ((lane & 3) << 1);
            float2 v0 = make_float2(acc[mi][ni][0], acc[mi][ni][1]);
            float2 v1 = make_float2(acc[mi][ni][2], acc[mi][ni][3]);
            *reinterpret_cast<float2*>(&dst[(size_t)(m0 + r0) * HID + col]) = v0;
            *reinterpret_cast<float2*>(&dst[(size_t)(m0 + r0 + 8) * HID + col]) = v1;
        }
    }

    // publish: all stores visible, then count this block done
    __threadfence();
    __syncthreads();
    if (tid == 0) atomicAdd(&g_hq_done, 1);
}

__global__ void __launch_bounds__(256, 2)
main_gemm_kernel(const __grid_constant__ CUtensorMap tmA,
                 const __grid_constant__ CUtensorMap tmB,
                 const float* __restrict__ q, const float* __restrict__ W1,
                 const float* __restrict__ b1, const float* __restrict__ W2,
                 const float* __restrict__ g1) {
    extern __shared__ __align__(16) char dsm[];
    uint32_t raw = (uint32_t)__cvta_generic_to_shared(dsm);
    uint32_t base = (raw + 1023u) & ~1023u;

    if (blockIdx.x < HQ_BLK) {
        __nv_bfloat16* sA = reinterpret_cast<__nv_bfloat16*>(
            dsm + (base - raw));
        hq_body(blockIdx.x, q, W1, sA, sA + BMH * BKT);
        return;
    }

    const uint32_t fullB = base + STAGES * STAGE_BYTES;
    const int bid = blockIdx.x - HQ_BLK;
    const int tid = threadIdx.x;
    const int lane = tid & 31;
    const int wid = tid >> 5;
    const int nt = bid & 7;      // 8 n-chunks of 128
    const int mt = bid >> 3;     // 216 m-tiles
    const int m0 = mt * 128;
    const int n0 = nt * 128;
    const int wm = (wid >> 2) * 64;     // 2 m-warps
    const int wn = (wid & 3) * 32;      // 4 n-warps, 32 cols each

    if (tid == 0) {
        for (int s = 0; s < STAGES; s++) mbar_init(fullB + s * 8, 1);
        asm volatile("fence.proxy.async.shared::cta;" ::: "memory");
    }
    __syncthreads();

    if (tid == 0) {
#pragma unroll
        for (int s = 0; s < STAGES; s++) {
            mbar_expect(fullB + s * 8, STAGE_BYTES);
            tma2d(base + s * STAGE_BYTES, &tmA, s * 64, m0, fullB + s * 8);
            tma2d(base + s * STAGE_BYTES + A_BYTES, &tmB, s * 64, n0,
                  fullB + s * 8);
        }
    }

    float acc[4][4][4];
#pragma unroll
    for (int a = 0; a < 4; a++)
#pragma unroll
        for (int b = 0; b < 4; b++)
#pragma unroll
            for (int c = 0; c < 4; c++) acc[a][b][c] = 0.f;

    for (int kt = 0; kt < MAIN_KT; kt++) {
        const int r = kt / 3;
        const int s = kt - r * 3;
        mbar_wait(fullB + s * 8, r & 1);

        const uint32_t sa = base + s * STAGE_BYTES;
        const uint32_t sb = sa + A_BYTES;

#pragma unroll
        for (int kh = 0; kh < 2; kh++) {
            uint32_t bbr[4][4];
#pragma unroll
            for (int ni = 0; ni < 4; ni++) {
                int nrow = wn + ni * 8 + (lane & 7);
                int chunk = kh * 4 + ((lane >> 3) & 3);
                uint32_t addr = sb + (uint32_t)(sw_off(nrow, chunk) * 2);
                ldsm4(bbr[ni][0], bbr[ni][1], bbr[ni][2], bbr[ni][3], addr);
            }
#pragma unroll
            for (int ks = 0; ks < 2; ks++) {
                uint32_t aa[4][4];
#pragma unroll
                for (int mi = 0; mi < 4; mi++) {
                    int row = wm + mi * 16 + (lane & 15);
                    int chunk = kh * 4 + ks * 2 + (lane >> 4);
                    uint32_t addr = sa + (uint32_t)(sw_off(row, chunk) * 2);
                    ldsm4(aa[mi][0], aa[mi][1], aa[mi][2], aa[mi][3], addr);
                }
#pragma unroll
                for (int mi = 0; mi < 4; mi++)
#pragma unroll
                    for (int ni = 0; ni < 4; ni++)
                        mma16816(acc[mi][ni], aa[mi], &bbr[ni][ks * 2]);
            }
        }

        __syncthreads();
        if (tid == 0 && kt + STAGES < MAIN_KT) {
            mbar_expect(fullB + s * 8, STAGE_BYTES);
            tma2d(base + s * STAGE_BYTES, &tmA, (kt + STAGES) * 64, m0,
                  fullB + s * 8);
            tma2d(base + s * STAGE_BYTES + A_BYTES, &tmB, (kt + STAGES) * 64,
                  n0, fullB + s * 8);
        }
    }

    // ---------------- wait for hq slices (normally already done) ----------
    {
        int done;
        do {
            asm volatile("ld.global.acquire.gpu.b32 %0, [%1];"
                         : "=r"(done) : "l"(&g_hq_done) : "memory");
        } while (done < HQ_BLK);
    }
    __syncthreads();   // pipeline smem now reusable by all threads

    // -------- cooperative hq slice-reduce into smem (<=5 rows x 128 cols) --
    float* shq = reinterpret_cast<float*>(dsm + (base - raw));
    const int qlo = m0 / NN;
    const int nq = (m0 + 127) / NN - qlo + 1;   // 4 or 5
    for (int idx = tid; idx < nq * 128; idx += 256) {
        int qr = idx >> 7;
        int c = idx & 127;
        size_t off = (size_t)(qlo + qr) * HID + n0 + c;
        shq[idx] = (g_hq4[0][off] + g_hq4[1][off]) +
                   (g_hq4[2][off] + g_hq4[3][off]);
    }
    __syncthreads();

    // ---------------- fused epilogue (hq from smem) ----------------
    const float s1 = g1[0] * rsqrtf(g_norm2[0]);
#pragma unroll
    for (int mi = 0; mi < 4; mi++) {
        int r0 = wm + mi * 16 + (lane >> 2);
        int grow0 = m0 + r0;
        int grow1 = grow0 + 8;
        const float* h0p = &shq[(grow0 / NN - qlo) * 128];
        const float* h1p = &shq[(grow1 / NN - qlo) * 128];
        float sum0 = 0.f, sum1 = 0.f;
#pragma unroll
        for (int ni = 0; ni < 4; ni++) {
            int lcol = wn + ni * 8 + ((lane & 3) << 1);
            int col = n0 + lcol;
#pragma unroll
            for (int j = 0; j < 2; j++) {
                float bb1 = b1[col + j];
                float ww2 = W2[col + j];
                float j0 = fmaxf(fmaf(s1, acc[mi][ni][j] + h0p[lcol + j], bb1), 0.f);
                float j1 = fmaxf(fmaf(s1, acc[mi][ni][2 + j] + h1p[lcol + j], bb1), 0.f);
                sum0 = fmaf(j0, ww2, sum0);
                sum1 = fmaf(j1, ww2, sum1);
            }
        }
        sum0 += __shfl_xor_sync(0xFFFFFFFFu, sum0, 1);
        sum0 += __shfl_xor_sync(0xFFFFFFFFu, sum0, 2);
        sum1 += __shfl_xor_sync(0xFFFFFFFFu, sum1, 1);
        sum1 += __shfl_xor_sync(0xFFFFFFFFu, sum1, 2);
        if ((lane & 3) == 0) {
            atomicAdd(&g_logits[grow0], sum0);
            atomicAdd(&g_logits[grow1], sum1);
        }
    }
}

// ---------------------------------------------------------------------------
__global__ void softmax_kernel(float* __restrict__ out,
                               const float* __restrict__ g2,
                               const float* __restrict__ b2) {
    int idx = blockIdx.x * blockDim.x + threadIdx.x;
    if (idx >= BB * NN) return;
    int b = idx / NN, n = idx % NN;
    float s2 = g2[0] * rsqrtf(g_norm2[1]);
    float b2v = b2[0];
    float vals[KK];
    float mx = -1e30f;
#pragma unroll
    for (int kk = 0; kk < KK; kk++) {
        float v = fmaf(s2, g_logits[(b * KK + kk) * NN + n], b2v);
        vals[kk] = v;
        mx = fmaxf(mx, v);
    }
    float sum = 0.f;
#pragma unroll
    for (int kk = 0; kk < KK; kk++) {
        vals[kk] = expf(vals[kk] - mx);
        sum += vals[kk];
    }
    float inv = 1.f / sum;
#pragma unroll
    for (int kk = 0; kk < KK; kk++)
        out[(b * KK + kk) * NN + n] = vals[kk] * inv;
}

// ---------------------------------------------------------------------------
typedef CUresult (*PFN_encodeTiled)(
    CUtensorMap*, CUtensorMapDataType, cuuint32_t, void*,
    const cuuint64_t*, const cuuint64_t*, const cuuint32_t*, const cuuint32_t*,
    CUtensorMapInterleave, CUtensorMapSwizzle, CUtensorMapL2promotion,
    CUtensorMapFloatOOBfill);

static void make_tm_bf16_2d(PFN_encodeTiled enc, CUtensorMap* tm, void* p,
                            uint64_t d0, uint64_t d1, uint32_t b0, uint32_t b1v) {
    cuuint64_t dims[2] = {d0, d1};
    cuuint64_t strides[1] = {d0 * 2};
    cuuint32_t box[2] = {b0, b1v};
    cuuint32_t es[2] = {1, 1};
    enc(tm, CU_TENSOR_MAP_DATA_TYPE_BFLOAT16, 2, p, dims, strides, box, es,
        CU_TENSOR_MAP_INTERLEAVE_NONE, CU_TENSOR_MAP_SWIZZLE_128B,
        CU_TENSOR_MAP_L2_PROMOTION_L2_128B, CU_TENSOR_MAP_FLOAT_OOB_FILL_NONE);
}

extern "C" void kernel_launch(void* const* d_in, const int* in_sizes, int n_in,
                              void* d_out, int out_size) {
    const float* v  = (const float*)d_in[0];
    const float* q  = (const float*)d_in[1];
    const float* W1 = (const float*)d_in[2];
    const float* g1 = (const float*)d_in[3];
    const float* b1 = (const float*)d_in[4];
    const float* W2 = (const float*)d_in[5];
    const float* g2 = (const float*)d_in[6];
    const float* b2 = (const float*)d_in[7];
    float* out = (float*)d_out;

    PFN_encodeTiled enc = nullptr;
    cudaDriverEntryPointQueryResult qres;
    cudaGetDriverEntryPoint("cuTensorMapEncodeTiled", (void**)&enc,
                            cudaEnableDefault, &qres);
    void *pv = nullptr, *pw = nullptr, *pn = nullptr, *pd = nullptr;
    cudaGetSymbolAddress(&pv, g_vb);
    cudaGetSymbolAddress(&pw, g_w1b);
    cudaGetSymbolAddress(&pn, g_norm2);
    cudaGetSymbolAddress(&pd, g_hq_done);
    CUtensorMap tmA, tmB;
    make_tm_bf16_2d(enc, &tmA, pv, VD, MROWS, 64, 128);
    make_tm_bf16_2d(enc, &tmB, pw, VD, HID, 64, 128);

    const int SMEM_SZ = STAGES * STAGE_BYTES + 1024 + 128;
    cudaFuncSetAttribute(main_gemm_kernel,
                         cudaFuncAttributeMaxDynamicSharedMemorySize, SMEM_SZ);

    // reset accumulators via graph-capturable memset nodes
    cudaMemsetAsync(pn, 0, 2 * sizeof(float));
    cudaMemsetAsync(pd, 0, sizeof(int));

    // prep (light regs): converts + norms + zero logits
    prep_kernel<<<PREP_GRID, 256>>>(v, W1, W2);

    // main: 192 hq blocks (overlap with main mainloop) + 1728 main tiles
    main_gemm_kernel<<<HQ_BLK + 216 * 8, 256, SMEM_SZ>>>(
        tmA, tmB, q, W1, b1, W2, g1);

    softmax_kernel<<<(BB * NN + 255) / 256, 256>>>(out, g2, b2);
}